// round 4
// baseline (speedup 1.0000x reference)
#include <cuda_runtime.h>

// Fused Canny-NMS-dilate for (32,3,512,512) fp32 -> (32,1,512,512) fp32.
// One kernel, 32x32 output tile per block, full halo staged through SMEM.

#define TILE 32
#define H 512
#define W 512
#define PLANE (512 * 512)

__constant__ int c_dY[8] = {0, 1, 1, 1, 0, -1, -1, -1};
__constant__ int c_dX[8] = {1, 1, 0, -1, -1, -1, 0, 1};

__global__ __launch_bounds__(256) void canny_fused_kernel(
    const float* __restrict__ in, float* __restrict__ out) {
    const int x0 = blockIdx.x * TILE;
    const int y0 = blockIdx.y * TILE;
    const int n  = blockIdx.z;
    const int tid = threadIdx.x;

    // Region sizes: gray 44x44, hblur 44x40, blur 40x40, mag 38x38, mask 36x36
    __shared__ float sG[44][48];          // gray (padded stride)
    __shared__ float sHb[44][40];         // horizontal blur
    __shared__ float sB[40][40];          // blurred
    __shared__ float sMag[38][40];        // |grad| (0 outside image)
    __shared__ unsigned char sSec[38][40];// direction sector 0..7
    __shared__ float sM[36][40];          // masked mag (0 outside image)
    __shared__ float sT[36][32];          // dilate row-max temp

    // Gaussian ksize=5 sigma=1, normalized
    const float w0 = 0.054488684549642945f;
    const float w1 = 0.24420134200323337f;
    const float w2 = 0.4026199485882447f;

    const float* base = in + (size_t)n * 3 * PLANE;

    // ---- Stage 1: gray with reflect indexing (covers blur's reflect pad) ----
    for (int idx = tid; idx < 44 * 44; idx += 256) {
        int i = idx / 44, j = idx % 44;
        int y = y0 - 6 + i, x = x0 - 6 + j;
        y = (y < 0) ? -y : y; y = (y > H - 1) ? (2 * H - 2 - y) : y;
        x = (x < 0) ? -x : x; x = (x > W - 1) ? (2 * W - 2 - x) : x;
        int o = y * W + x;
        float r = base[2 * PLANE + o];   // after channel flip: 0.299 * old ch2
        float g = base[1 * PLANE + o];
        float b = base[o];
        sG[i][j] = 0.299f * r + 0.587f * g + 0.114f * b;
    }
    __syncthreads();

    // ---- Stage 2: horizontal Gaussian ----
    for (int idx = tid; idx < 44 * 40; idx += 256) {
        int i = idx / 40, j = idx % 40;
        sHb[i][j] = w0 * (sG[i][j] + sG[i][j + 4])
                  + w1 * (sG[i][j + 1] + sG[i][j + 3])
                  + w2 * sG[i][j + 2];
    }
    __syncthreads();

    // ---- Stage 3: vertical Gaussian ----
    for (int idx = tid; idx < 40 * 40; idx += 256) {
        int i = idx / 40, j = idx % 40;
        sB[i][j] = w0 * (sHb[i][j] + sHb[i + 4][j])
                 + w1 * (sHb[i + 1][j] + sHb[i + 3][j])
                 + w2 * sHb[i + 2][j];
    }
    __syncthreads();

    // ---- Stage 4: Sobel (edge-pad via clamp) + magnitude + sector ----
    for (int idx = tid; idx < 38 * 38; idx += 256) {
        int i = idx / 38, j = idx % 38;
        int y = y0 - 3 + i, x = x0 - 3 + j;
        float mag = 0.0f;
        unsigned char sec = 0;
        if ((unsigned)y < (unsigned)H && (unsigned)x < (unsigned)W) {
            int yc = i + 1, xc = j + 1;                 // sB index of (y, x)
            int ym = max(y - 1, 0) - (y0 - 4);
            int yp = min(y + 1, H - 1) - (y0 - 4);
            int xm = max(x - 1, 0) - (x0 - 4);
            int xp = min(x + 1, W - 1) - (x0 - 4);
            float b00 = sB[ym][xm], b01 = sB[ym][xc], b02 = sB[ym][xp];
            float b10 = sB[yc][xm],                    b12 = sB[yc][xp];
            float b20 = sB[yp][xm], b21 = sB[yp][xc], b22 = sB[yp][xp];
            float gx = ((b02 - b00) + 2.0f * (b12 - b10) + (b22 - b20)) * 0.125f;
            float gy = ((b20 - b00) + 2.0f * (b21 - b01) + (b22 - b02)) * 0.125f;
            mag = sqrtf(gx * gx + gy * gy + 1e-6f);
            // round(atan2(gy,gx)/45deg) mod 8 via comparisons.
            // tan(22.5) / tan(67.5); inclusive bounds match round-half-to-even.
            float ax = fabsf(gx), ay = fabsf(gy);
            if (ay <= 0.41421356237309503f * ax)
                sec = (gx >= 0.0f) ? 0 : 4;
            else if (ay >= 2.4142135623730951f * ax)
                sec = (gy >= 0.0f) ? 2 : 6;
            else
                sec = (gy > 0.0f) ? ((gx > 0.0f) ? 1 : 3)
                                  : ((gx > 0.0f) ? 7 : 5);
        }
        sMag[i][j] = mag;   // 0 outside image == nms zero-pad semantics
        sSec[i][j] = sec;
    }
    __syncthreads();

    // ---- Stage 5: NMS mask ----
    for (int idx = tid; idx < 36 * 36; idx += 256) {
        int i = idx / 36, j = idx % 36;
        int y = y0 - 2 + i, x = x0 - 2 + j;
        float m = 0.0f;
        if ((unsigned)y < (unsigned)H && (unsigned)x < (unsigned)W) {
            int s = sSec[i + 1][j + 1];
            int dy = c_dY[s], dx = c_dX[s];
            float c  = sMag[i + 1][j + 1];
            float p1 = sMag[i + 1 + dy][j + 1 + dx];
            float p2 = sMag[i + 1 - dy][j + 1 - dx];
            m = (c > p1 && c > p2) ? c : 0.0f;   // min(pos,neg) > 0
        }
        sM[i][j] = m;   // masked mag >= 0, so 0-pad == ref's -10000 pad for max
    }
    __syncthreads();

    // ---- Stage 6: 5x5 max-dilate, separable (rows then cols) ----
    for (int idx = tid; idx < 36 * 32; idx += 256) {
        int i = idx / 32, j = idx % 32;
        float v = sM[i][j];
        v = fmaxf(v, sM[i][j + 1]);
        v = fmaxf(v, sM[i][j + 2]);
        v = fmaxf(v, sM[i][j + 3]);
        v = fmaxf(v, sM[i][j + 4]);
        sT[i][j] = v;
    }
    __syncthreads();

    float* ob = out + (size_t)n * PLANE;
    for (int idx = tid; idx < 32 * 32; idx += 256) {
        int i = idx / 32, j = idx % 32;
        float v = sT[i][j];
        v = fmaxf(v, sT[i + 1][j]);
        v = fmaxf(v, sT[i + 2][j]);
        v = fmaxf(v, sT[i + 3][j]);
        v = fmaxf(v, sT[i + 4][j]);
        ob[(y0 + i) * W + (x0 + j)] = v;
    }
}

extern "C" void kernel_launch(void* const* d_in, const int* in_sizes, int n_in,
                              void* d_out, int out_size) {
    const float* x = (const float*)d_in[0];
    float* out = (float*)d_out;
    dim3 grid(W / TILE, H / TILE, 32);
    canny_fused_kernel<<<grid, 256>>>(x, out);
}

// round 5
// speedup vs baseline: 1.2271x; 1.2271x over previous
#include <cuda_runtime.h>

// Fused Canny-NMS-dilate for (32,3,512,512) fp32 -> (32,1,512,512) fp32.
// 64x32 output tile, 256 threads as 32x8, no integer div/mod, aliased smem.

#define TW 64
#define TH 32
#define H 512
#define W 512
#define PLANE (512 * 512)

__constant__ int c_dY[8] = {0, 1, 1, 1, 0, -1, -1, -1};
__constant__ int c_dX[8] = {1, 1, 0, -1, -1, -1, 0, 1};

// Region geometry (rows x cols, smem stride):
//   gray  44 x 76  (stride 80)  bufA
//   hblur 44 x 72  (stride 72)  bufB
//   blur  40 x 72  (stride 72)  bufC
//   mag   38 x 70  (stride 72)  bufA (gray dead)   + sSec bytes
//   mask  36 x 68  (stride 72)  bufB (hblur dead)
//   rowmx 36 x 64  (stride 64)  bufC (blur dead)

__global__ __launch_bounds__(256) void canny_fused_kernel(
    const float* __restrict__ in, float* __restrict__ out) {
    const int x0 = blockIdx.x * TW;
    const int y0 = blockIdx.y * TH;
    const int n  = blockIdx.z;
    const int tx = threadIdx.x & 31;
    const int ty = threadIdx.x >> 5;

    __shared__ float bufA[44 * 80];            // gray -> mag
    __shared__ float bufB[44 * 72];            // hblur -> mask
    __shared__ float bufC[40 * 72];            // blur -> rowmax
    __shared__ unsigned char sSec[38 * 72];    // sector

    const float w0 = 0.054488684549642945f;
    const float w1 = 0.24420134200323337f;
    const float w2 = 0.4026199485882447f;

    const float* base = in + (size_t)n * 3 * PLANE;

    // ---- Stage 1: gray with reflect indexing (44 rows x 76 cols) ----
    for (int i = ty; i < 44; i += 8) {
        int y = y0 - 6 + i;
        y = (y < 0) ? -y : y; y = (y > H - 1) ? (2 * H - 2 - y) : y;
        const float* r0 = base + y * W;
        float* gr = &bufA[i * 80];
#pragma unroll
        for (int jj = 0; jj < 3; ++jj) {
            int j = tx + jj * 32;
            if (jj < 2 || j < 76) {
                int x = x0 - 6 + j;
                x = (x < 0) ? -x : x; x = (x > W - 1) ? (2 * W - 2 - x) : x;
                float b = r0[x];
                float g = r0[PLANE + x];
                float r = r0[2 * PLANE + x];
                gr[j] = fmaf(0.299f, r, fmaf(0.587f, g, 0.114f * b));
            }
        }
    }
    __syncthreads();

    // ---- Stage 2: horizontal Gaussian (44 x 72) ----
    for (int i = ty; i < 44; i += 8) {
        const float* g = &bufA[i * 80];
        float* hb = &bufB[i * 72];
#pragma unroll
        for (int jj = 0; jj < 3; ++jj) {
            int j = tx + jj * 32;
            if (jj < 2 || j < 72) {
                hb[j] = fmaf(w0, g[j] + g[j + 4],
                        fmaf(w1, g[j + 1] + g[j + 3], w2 * g[j + 2]));
            }
        }
    }
    __syncthreads();

    // ---- Stage 3: vertical Gaussian (40 x 72) ----
    for (int i = ty; i < 40; i += 8) {
        const float* h0 = &bufB[i * 72];
        float* bl = &bufC[i * 72];
#pragma unroll
        for (int jj = 0; jj < 3; ++jj) {
            int j = tx + jj * 32;
            if (jj < 2 || j < 72) {
                bl[j] = fmaf(w0, h0[j] + h0[4 * 72 + j],
                        fmaf(w1, h0[1 * 72 + j] + h0[3 * 72 + j],
                             w2 * h0[2 * 72 + j]));
            }
        }
    }
    __syncthreads();

    // ---- Stage 4: Sobel + magnitude + sector (38 x 70), into bufA ----
    for (int i = ty; i < 38; i += 8) {
        int y = y0 - 3 + i;
#pragma unroll
        for (int jj = 0; jj < 3; ++jj) {
            int j = tx + jj * 32;
            if (jj < 2 || j < 70) {
                int x = x0 - 3 + j;
                float mag = 0.0f;
                unsigned char sec = 0;
                if ((unsigned)y < (unsigned)H && (unsigned)x < (unsigned)W) {
                    int yc = i + 1, xc = j + 1;           // bufC index of (y,x)
                    int ym = max(y - 1, 0) - (y0 - 4);
                    int yp = min(y + 1, H - 1) - (y0 - 4);
                    int xm = max(x - 1, 0) - (x0 - 4);
                    int xp = min(x + 1, W - 1) - (x0 - 4);
                    float b00 = bufC[ym * 72 + xm], b01 = bufC[ym * 72 + xc], b02 = bufC[ym * 72 + xp];
                    float b10 = bufC[yc * 72 + xm],                           b12 = bufC[yc * 72 + xp];
                    float b20 = bufC[yp * 72 + xm], b21 = bufC[yp * 72 + xc], b22 = bufC[yp * 72 + xp];
                    float gx = ((b02 - b00) + 2.0f * (b12 - b10) + (b22 - b20)) * 0.125f;
                    float gy = ((b20 - b00) + 2.0f * (b21 - b01) + (b22 - b02)) * 0.125f;
                    mag = sqrtf(fmaf(gx, gx, fmaf(gy, gy, 1e-6f)));
                    float ax = fabsf(gx), ay = fabsf(gy);
                    if (ay <= 0.41421356237309503f * ax)
                        sec = (gx >= 0.0f) ? 0 : 4;
                    else if (ay >= 2.4142135623730951f * ax)
                        sec = (gy >= 0.0f) ? 2 : 6;
                    else
                        sec = (gy > 0.0f) ? ((gx > 0.0f) ? 1 : 3)
                                          : ((gx > 0.0f) ? 7 : 5);
                }
                bufA[i * 72 + j] = mag;     // 0 outside image == zero-pad
                sSec[i * 72 + j] = sec;
            }
        }
    }
    __syncthreads();

    // ---- Stage 5: NMS mask (36 x 68), into bufB ----
    for (int i = ty; i < 36; i += 8) {
        int y = y0 - 2 + i;
#pragma unroll
        for (int jj = 0; jj < 3; ++jj) {
            int j = tx + jj * 32;
            if (jj < 2 || j < 68) {
                int x = x0 - 2 + j;
                float m = 0.0f;
                if ((unsigned)y < (unsigned)H && (unsigned)x < (unsigned)W) {
                    int s = sSec[(i + 1) * 72 + j + 1];
                    int dy = c_dY[s], dx = c_dX[s];
                    float c  = bufA[(i + 1) * 72 + j + 1];
                    float p1 = bufA[(i + 1 + dy) * 72 + j + 1 + dx];
                    float p2 = bufA[(i + 1 - dy) * 72 + j + 1 - dx];
                    m = (c > p1 && c > p2) ? c : 0.0f;
                }
                bufB[i * 72 + j] = m;
            }
        }
    }
    __syncthreads();

    // ---- Stage 6: row-max of 5 (36 x 64), into bufC ----
    for (int i = ty; i < 36; i += 8) {
        const float* mr = &bufB[i * 72];
        float* tr = &bufC[i * 64];
#pragma unroll
        for (int jj = 0; jj < 2; ++jj) {
            int j = tx + jj * 32;
            float v = fmaxf(fmaxf(fmaxf(mr[j], mr[j + 1]), fmaxf(mr[j + 2], mr[j + 3])), mr[j + 4]);
            tr[j] = v;
        }
    }
    __syncthreads();

    // ---- Stage 7: col-max of 5, write output (32 x 64) ----
    float* ob = out + (size_t)n * PLANE;
    for (int i = ty; i < 32; i += 8) {
        const float* t0 = &bufC[i * 64];
#pragma unroll
        for (int jj = 0; jj < 2; ++jj) {
            int j = tx + jj * 32;
            float v = fmaxf(fmaxf(fmaxf(t0[j], t0[64 + j]), fmaxf(t0[128 + j], t0[192 + j])), t0[256 + j]);
            ob[(y0 + i) * W + (x0 + j)] = v;
        }
    }
}

extern "C" void kernel_launch(void* const* d_in, const int* in_sizes, int n_in,
                              void* d_out, int out_size) {
    const float* x = (const float*)d_in[0];
    float* out = (float*)d_out;
    dim3 grid(W / TW, H / TH, 32);
    canny_fused_kernel<<<grid, 256>>>(x, out);
}

// round 6
// speedup vs baseline: 1.5480x; 1.2615x over previous
#include <cuda_runtime.h>

// Fused Canny-NMS-dilate for (32,3,512,512) fp32 -> (32,1,512,512) fp32.
// 64x32 tile, 256 threads (32x8), vertical register blocking + float2 smem ops.

#define TW 64
#define TH 32
#define H 512
#define W 512
#define PLANE (512 * 512)

// smem regions (rows x cols, stride in floats):
//   gray  44 x 76 (stride 80) bufA     -> mag  38 x 70 (stride 72) bufA
//   hblur 44 x 72 (stride 72) bufB     -> mask 36 x 68 (stride 72) bufB
//   blur  40 x 72 (stride 72) bufC     -> rowmax 36 x 64 (stride 64) bufC
//   sDel  38 x 72 int16 (NMS neighbor offset, sign-free)

__global__ __launch_bounds__(256) void canny_fused_kernel(
    const float* __restrict__ in, float* __restrict__ out) {
    const int x0 = blockIdx.x * TW;
    const int y0 = blockIdx.y * TH;
    const int n  = blockIdx.z;
    const int tx = threadIdx.x & 31;
    const int ty = threadIdx.x >> 5;

    __shared__ float bufA[44 * 80];
    __shared__ float bufB[44 * 72];
    __shared__ float bufC[40 * 72];
    __shared__ short sDel[38 * 72];

    const float w0 = 0.054488684549642945f;
    const float w1 = 0.24420134200323337f;
    const float w2 = 0.4026199485882447f;

    const float* base = in + (size_t)n * 3 * PLANE;

    // ---- Stage 1: gray with reflect (44 x 76). x-reflect hoisted. ----
    int xs0, xs1, xs2;
    {
        int x = x0 - 6 + tx;      x = (x < 0) ? -x : x; xs0 = (x > 511) ? 1022 - x : x;
        x = x0 + 26 + tx;                                xs1 = (x > 511) ? 1022 - x : x;
        x = x0 + 58 + tx;                                xs2 = (x > 511) ? 1022 - x : x;
    }
    for (int i = ty; i < 44; i += 8) {
        int y = y0 - 6 + i; y = (y < 0) ? -y : y; y = (y > 511) ? 1022 - y : y;
        const float* r0 = base + y * W;
        float* gr = &bufA[i * 80];
        gr[tx]      = fmaf(0.299f, r0[2 * PLANE + xs0], fmaf(0.587f, r0[PLANE + xs0], 0.114f * r0[xs0]));
        gr[tx + 32] = fmaf(0.299f, r0[2 * PLANE + xs1], fmaf(0.587f, r0[PLANE + xs1], 0.114f * r0[xs1]));
        if (tx < 12)
            gr[tx + 64] = fmaf(0.299f, r0[2 * PLANE + xs2], fmaf(0.587f, r0[PLANE + xs2], 0.114f * r0[xs2]));
    }
    __syncthreads();

    // ---- Stage 2: horizontal Gaussian (44 x 72), float2 pairs ----
    for (int i = ty; i < 44; i += 8) {
        const float2* g2 = (const float2*)&bufA[i * 80];
        float2 e0 = g2[tx], e1 = g2[tx + 1], e2 = g2[tx + 2];
        float2 o;
        o.x = fmaf(w0, e0.x + e2.x, fmaf(w1, e0.y + e1.y, w2 * e1.x));
        o.y = fmaf(w0, e0.y + e2.y, fmaf(w1, e1.x + e2.x, w2 * e1.y));
        ((float2*)&bufB[i * 72])[tx] = o;
        if (tx < 8) {
            const float* g = &bufA[i * 80 + 64];
            bufB[i * 72 + 64 + tx] =
                fmaf(w0, g[tx] + g[tx + 4], fmaf(w1, g[tx + 1] + g[tx + 3], w2 * g[tx + 2]));
        }
    }
    __syncthreads();

    // ---- Stage 3: vertical Gaussian (40 x 72), 5 contiguous rows/thread ----
    {
        const int r0r = ty * 5;
        float2 h[9];
#pragma unroll
        for (int r = 0; r < 9; ++r) h[r] = ((const float2*)&bufB[(r0r + r) * 72])[tx];
#pragma unroll
        for (int v = 0; v < 5; ++v) {
            float2 o;
            o.x = fmaf(w0, h[v].x + h[v + 4].x, fmaf(w1, h[v + 1].x + h[v + 3].x, w2 * h[v + 2].x));
            o.y = fmaf(w0, h[v].y + h[v + 4].y, fmaf(w1, h[v + 1].y + h[v + 3].y, w2 * h[v + 2].y));
            ((float2*)&bufC[(r0r + v) * 72])[tx] = o;
        }
        if (tx < 8) {
            float hh[9];
#pragma unroll
            for (int r = 0; r < 9; ++r) hh[r] = bufB[(r0r + r) * 72 + 64 + tx];
#pragma unroll
            for (int v = 0; v < 5; ++v)
                bufC[(r0r + v) * 72 + 64 + tx] =
                    fmaf(w0, hh[v] + hh[v + 4], fmaf(w1, hh[v + 1] + hh[v + 3], w2 * hh[v + 2]));
        }
    }
    __syncthreads();

    // ---- Stage 4: Sobel + mag + NMS-delta (38 x 70), rolling row stream ----
    {
        const int r0m = min(ty * 5, 33);      // ragged tail via harmless duplicate rows
#pragma unroll
        for (int pass = 0; pass < 2; ++pass) {
            if (pass == 1 && tx >= 3) break;
            const int jb = (pass == 0) ? 2 * tx : 64 + 2 * tx;
            const int x = x0 - 3 + jb;
            const int x2 = x + 1;
            const bool xin0 = (unsigned)x < (unsigned)W;
            const bool xin1 = (unsigned)x2 < (unsigned)W;
            const bool lc0 = (x > 0), rc0 = (x < W - 1);
            const bool lc1 = (x2 > 0), rc1 = (x2 < W - 1);

            // row loader: stream position r -> (s0,d0,s1,d1)
            float s0p, d0p, s1p, d1p, s0c, d0c, s1c, d1c;
#define LOADROW(R, S0, D0, S1, D1)                                            \
            {                                                                  \
                int yr = y0 - 3 + r0m + (R);                                   \
                yr = max(0, min(yr, H - 1));                                   \
                const float* br = &bufC[(yr - y0 + 4) * 72 + jb];              \
                float b0 = br[0], b1 = br[1], b2 = br[2], b3 = br[3];          \
                float l0 = lc0 ? b0 : b1, r0_ = rc0 ? b2 : b1;                 \
                float l1 = lc1 ? b1 : b2, r1_ = rc1 ? b3 : b2;                 \
                S0 = l0 + 2.0f * b1 + r0_; D0 = r0_ - l0;                      \
                S1 = l1 + 2.0f * b2 + r1_; D1 = r1_ - l1;                      \
            }
            LOADROW(-1, s0p, d0p, s1p, d1p)
            LOADROW(0, s0c, d0c, s1c, d1c)
#pragma unroll
            for (int v = 0; v < 5; ++v) {
                float s0n, d0n, s1n, d1n;
                LOADROW(v + 1, s0n, d0n, s1n, d1n)
                const int i = r0m + v;
                const int y = y0 - 3 + i;
                const bool yin = (unsigned)y < (unsigned)H;

                float gy0 = (s0n - s0p) * 0.125f;
                float gx0 = (d0p + 2.0f * d0c + d0n) * 0.125f;
                float gy1 = (s1n - s1p) * 0.125f;
                float gx1 = (d1p + 2.0f * d1c + d1n) * 0.125f;

                float m0 = 0.0f, m1 = 0.0f;
                short e0 = 1, e1 = 1;
                if (yin) {
                    if (xin0) {
                        m0 = sqrtf(fmaf(gx0, gx0, fmaf(gy0, gy0, 1e-6f)));
                        float ax = fabsf(gx0), ay = fabsf(gy0);
                        if (ay <= 0.41421356237309503f * ax) e0 = 1;
                        else if (ay >= 2.4142135623730951f * ax) e0 = 72;
                        else e0 = ((gx0 > 0.0f) == (gy0 > 0.0f)) ? 73 : 71;
                    }
                    if (xin1) {
                        m1 = sqrtf(fmaf(gx1, gx1, fmaf(gy1, gy1, 1e-6f)));
                        float ax = fabsf(gx1), ay = fabsf(gy1);
                        if (ay <= 0.41421356237309503f * ax) e1 = 1;
                        else if (ay >= 2.4142135623730951f * ax) e1 = 72;
                        else e1 = ((gx1 > 0.0f) == (gy1 > 0.0f)) ? 73 : 71;
                    }
                }
                *(float2*)&bufA[i * 72 + jb] = make_float2(m0, m1);
                *(short2*)&sDel[i * 72 + jb] = make_short2(e0, e1);

                s0p = s0c; d0p = d0c; s1p = s1c; d1p = d1c;
                s0c = s0n; d0c = d0n; s1c = s1n; d1c = d1n;
            }
#undef LOADROW
        }
    }
    __syncthreads();

    // ---- Stage 5: NMS mask (36 x 68). |delta| works: min(pos,neg) symmetric ----
    for (int i = ty; i < 36; i += 8) {
        const int y = y0 - 2 + i;
        const bool yin = (unsigned)y < (unsigned)H;
#pragma unroll
        for (int jj = 0; jj < 3; ++jj) {
            int j = tx + jj * 32;
            if (jj < 2 || tx < 4) {
                int x = x0 - 2 + j;
                float m = 0.0f;
                if (yin && (unsigned)x < (unsigned)W) {
                    int ci = (i + 1) * 72 + j + 1;
                    int d = sDel[ci];
                    float c = bufA[ci];
                    float p1 = bufA[ci + d];
                    float p2 = bufA[ci - d];
                    m = (c > p1 && c > p2) ? c : 0.0f;
                }
                bufB[i * 72 + j] = m;
            }
        }
    }
    __syncthreads();

    // ---- Stage 6: horizontal 5-max (36 x 64), float2 pairs ----
    for (int i = ty; i < 36; i += 8) {
        const float2* m2 = (const float2*)&bufB[i * 72];
        float2 a = m2[tx], b = m2[tx + 1], c = m2[tx + 2];
        float common = fmaxf(fmaxf(a.y, b.x), fmaxf(b.y, c.x));
        ((float2*)&bufC[i * 64])[tx] = make_float2(fmaxf(common, a.x), fmaxf(common, c.y));
    }
    __syncthreads();

    // ---- Stage 7: vertical 5-max, 4 contiguous rows/thread, float2 STG ----
    {
        const int r0o = ty * 4;
        float2 t[8];
#pragma unroll
        for (int r = 0; r < 8; ++r) t[r] = ((const float2*)&bufC[(r0o + r) * 64])[tx];
        float* ob = out + (size_t)n * PLANE;
#pragma unroll
        for (int v = 0; v < 4; ++v) {
            float2 o;
            float cx = fmaxf(fmaxf(t[v + 1].x, t[v + 2].x), fmaxf(t[v + 3].x, t[v + 4].x));
            float cy = fmaxf(fmaxf(t[v + 1].y, t[v + 2].y), fmaxf(t[v + 3].y, t[v + 4].y));
            o.x = fmaxf(cx, t[v].x);
            o.y = fmaxf(cy, t[v].y);
            *(float2*)&ob[(size_t)(y0 + r0o + v) * W + x0 + 2 * tx] = o;
        }
    }
}

extern "C" void kernel_launch(void* const* d_in, const int* in_sizes, int n_in,
                              void* d_out, int out_size) {
    const float* x = (const float*)d_in[0];
    float* out = (float*)d_out;
    dim3 grid(W / TW, H / TH, 32);
    canny_fused_kernel<<<grid, 256>>>(x, out);
}

// round 8
// speedup vs baseline: 1.7376x; 1.1225x over previous
#include <cuda_runtime.h>

// Fused Canny-NMS-dilate for (32,3,512,512) fp32 -> (32,1,512,512) fp32.
// 64x32 tile, 256 threads (32x8). Interior tiles take a clamp-free fast path.

#define H 512
#define W 512
#define PLANE (512 * 512)

struct __align__(16) Smem {
    float bufA[44 * 80];   // gray -> mag (stride 80 then 72)
    float bufB[44 * 72];   // hblur -> mask
    float bufC[40 * 72];   // blur -> rowmax (stride 72 then 64)
    short sDel[38 * 72];   // NMS neighbor offset (sign-free)
};

__device__ __forceinline__ void mag_sector(float gx, float gy, float& m, short& e) {
    m = sqrtf(fmaf(gx, gx, fmaf(gy, gy, 1e-6f)));
    float ax = fabsf(gx), ay = fabsf(gy);
    if (ay <= 0.41421356237309503f * ax)      e = 1;    // horizontal
    else if (ay >= 2.4142135623730951f * ax)  e = 72;   // vertical
    else e = ((gx > 0.0f) == (gy > 0.0f)) ? 73 : 71;    // diagonals
}

template <bool BORDER>
__device__ __forceinline__ void canny_tile(
    Smem& s, const float* __restrict__ base, float* __restrict__ ob,
    int x0, int y0, int tx, int ty, int tid) {

    const float w0 = 0.054488684549642945f;
    const float w1 = 0.24420134200323337f;
    const float w2 = 0.4026199485882447f;

    // ---- Stage 1: gray (44 x 76), reflect only on border ----
    int xs0, xs1, xs2;
    if (BORDER) {
        int x = x0 - 6 + tx; x = (x < 0) ? -x : x; xs0 = (x > 511) ? 1022 - x : x;
        x = x0 + 26 + tx;                           xs1 = (x > 511) ? 1022 - x : x;
        x = x0 + 58 + tx;                           xs2 = (x > 511) ? 1022 - x : x;
    } else {
        xs0 = x0 - 6 + tx; xs1 = x0 + 26 + tx; xs2 = x0 + 58 + tx;
    }
    for (int i = ty; i < 44; i += 8) {
        int y = y0 - 6 + i;
        if (BORDER) { y = (y < 0) ? -y : y; y = (y > 511) ? 1022 - y : y; }
        const float* r0 = base + y * W;
        float* gr = &s.bufA[i * 80];
        gr[tx]      = fmaf(0.299f, r0[2 * PLANE + xs0], fmaf(0.587f, r0[PLANE + xs0], 0.114f * r0[xs0]));
        gr[tx + 32] = fmaf(0.299f, r0[2 * PLANE + xs1], fmaf(0.587f, r0[PLANE + xs1], 0.114f * r0[xs1]));
        if (tx < 12)
            gr[tx + 64] = fmaf(0.299f, r0[2 * PLANE + xs2], fmaf(0.587f, r0[PLANE + xs2], 0.114f * r0[xs2]));
    }
    __syncthreads();

    // ---- Stage 2: horizontal Gaussian (44 x 72), float2 pairs ----
    for (int i = ty; i < 44; i += 8) {
        const float2* g2 = (const float2*)&s.bufA[i * 80];
        float2 e0 = g2[tx], e1 = g2[tx + 1], e2 = g2[tx + 2];
        float2 o;
        o.x = fmaf(w0, e0.x + e2.x, fmaf(w1, e0.y + e1.y, w2 * e1.x));
        o.y = fmaf(w0, e0.y + e2.y, fmaf(w1, e1.x + e2.x, w2 * e1.y));
        ((float2*)&s.bufB[i * 72])[tx] = o;
        if (tx < 8) {
            const float* g = &s.bufA[i * 80 + 64];
            s.bufB[i * 72 + 64 + tx] =
                fmaf(w0, g[tx] + g[tx + 4], fmaf(w1, g[tx + 1] + g[tx + 3], w2 * g[tx + 2]));
        }
    }
    __syncthreads();

    // ---- Stage 3: vertical Gaussian (40 x 72), 5 contiguous rows/thread ----
    {
        const int r0r = ty * 5;
        float2 h[9];
#pragma unroll
        for (int r = 0; r < 9; ++r) h[r] = ((const float2*)&s.bufB[(r0r + r) * 72])[tx];
#pragma unroll
        for (int v = 0; v < 5; ++v) {
            float2 o;
            o.x = fmaf(w0, h[v].x + h[v + 4].x, fmaf(w1, h[v + 1].x + h[v + 3].x, w2 * h[v + 2].x));
            o.y = fmaf(w0, h[v].y + h[v + 4].y, fmaf(w1, h[v + 1].y + h[v + 3].y, w2 * h[v + 2].y));
            ((float2*)&s.bufC[(r0r + v) * 72])[tx] = o;
        }
        if (tx < 8) {
            float hh[9];
#pragma unroll
            for (int r = 0; r < 9; ++r) hh[r] = s.bufB[(r0r + r) * 72 + 64 + tx];
#pragma unroll
            for (int v = 0; v < 5; ++v)
                s.bufC[(r0r + v) * 72 + 64 + tx] =
                    fmaf(w0, hh[v] + hh[v + 4], fmaf(w1, hh[v + 1] + hh[v + 3], w2 * hh[v + 2]));
        }
    }
    __syncthreads();

    // ---- Stage 4a: Sobel + mag + delta, cols 0..63 (rolling stream) ----
    {
        const int r0m = min(ty * 5, 33);   // ragged tail: duplicate rows, harmless
        const int jb = 2 * tx;
        const int x = x0 - 3 + jb;
        bool xin0 = true, xin1 = true, lc0 = true, rc0 = true, lc1 = true, rc1 = true;
        if (BORDER) {
            xin0 = (unsigned)x < (unsigned)W;
            xin1 = (unsigned)(x + 1) < (unsigned)W;
            lc0 = (x > 0); rc0 = (x < W - 1);
            lc1 = (x + 1 > 0); rc1 = (x + 1 < W - 1);
        }
        float s0p, d0p, s1p, d1p, s0c, d0c, s1c, d1c;
#define LOADROW(R, S0, D0, S1, D1)                                             \
        {                                                                      \
            int rr;                                                            \
            if (BORDER) {                                                      \
                int yr = y0 - 3 + r0m + (R);                                   \
                yr = max(0, min(yr, H - 1));                                   \
                rr = yr - y0 + 4;                                              \
            } else {                                                           \
                rr = r0m + (R) + 1;                                            \
            }                                                                  \
            const float2* br = (const float2*)&s.bufC[rr * 72 + jb];           \
            float2 p = br[0], q = br[1];                                       \
            float l0 = BORDER ? (lc0 ? p.x : p.y) : p.x;                       \
            float r0_ = BORDER ? (rc0 ? q.x : p.y) : q.x;                      \
            float l1 = BORDER ? (lc1 ? p.y : q.x) : p.y;                       \
            float r1_ = BORDER ? (rc1 ? q.y : q.x) : q.y;                      \
            S0 = l0 + 2.0f * p.y + r0_; D0 = r0_ - l0;                         \
            S1 = l1 + 2.0f * q.x + r1_; D1 = r1_ - l1;                         \
        }
        LOADROW(-1, s0p, d0p, s1p, d1p)
        LOADROW(0, s0c, d0c, s1c, d1c)
#pragma unroll
        for (int v = 0; v < 5; ++v) {
            float s0n, d0n, s1n, d1n;
            LOADROW(v + 1, s0n, d0n, s1n, d1n)
            const int i = r0m + v;
            float gy0 = (s0n - s0p) * 0.125f;
            float gx0 = (d0p + 2.0f * d0c + d0n) * 0.125f;
            float gy1 = (s1n - s1p) * 0.125f;
            float gx1 = (d1p + 2.0f * d1c + d1n) * 0.125f;

            float m0 = 0.0f, m1 = 0.0f;
            short e0 = 1, e1 = 1;
            if (BORDER) {
                bool yin = (unsigned)(y0 - 3 + i) < (unsigned)H;
                if (yin && xin0) mag_sector(gx0, gy0, m0, e0);
                if (yin && xin1) mag_sector(gx1, gy1, m1, e1);
            } else {
                mag_sector(gx0, gy0, m0, e0);
                mag_sector(gx1, gy1, m1, e1);
            }
            *(float2*)&s.bufA[i * 72 + jb] = make_float2(m0, m1);
            *(short2*)&s.sDel[i * 72 + jb] = make_short2(e0, e1);

            s0p = s0c; d0p = d0c; s1p = s1c; d1p = d1c;
            s0c = s0n; d0c = d0n; s1c = s1n; d1c = d1n;
        }
#undef LOADROW
    }

    // ---- Stage 4b: cols 64..69 as flat tasks (38 rows x 3 float2 = 114) ----
    if (tid < 114) {
        const int i = tid / 3;
        const int c = tid - 3 * i;
        const int jb = 64 + 2 * c;
        float m0 = 0.0f, m1 = 0.0f;
        short e0 = 1, e1 = 1;
        if (BORDER) {
            const int y = y0 - 3 + i;
            if ((unsigned)y < (unsigned)H) {
                int ymi = max(y - 1, 0) - (y0 - 4);
                int ypi = min(y + 1, H - 1) - (y0 - 4);
                int yci = i + 1;
#pragma unroll
                for (int k = 0; k < 2; ++k) {
                    int xk = x0 - 3 + jb + k;
                    if ((unsigned)xk < (unsigned)W) {
                        int xm = max(xk - 1, 0) - (x0 - 4);
                        int xp = min(xk + 1, W - 1) - (x0 - 4);
                        int xc = jb + 1 + k;
                        float b00 = s.bufC[ymi * 72 + xm], b01 = s.bufC[ymi * 72 + xc], b02 = s.bufC[ymi * 72 + xp];
                        float b10 = s.bufC[yci * 72 + xm],                              b12 = s.bufC[yci * 72 + xp];
                        float b20 = s.bufC[ypi * 72 + xm], b21 = s.bufC[ypi * 72 + xc], b22 = s.bufC[ypi * 72 + xp];
                        float gx = ((b02 - b00) + 2.0f * (b12 - b10) + (b22 - b20)) * 0.125f;
                        float gy = ((b20 - b00) + 2.0f * (b21 - b01) + (b22 - b02)) * 0.125f;
                        if (k == 0) mag_sector(gx, gy, m0, e0);
                        else        mag_sector(gx, gy, m1, e1);
                    }
                }
            }
        } else {
            const float2* rU = (const float2*)&s.bufC[i * 72 + jb];
            const float2* rC = (const float2*)&s.bufC[(i + 1) * 72 + jb];
            const float2* rD = (const float2*)&s.bufC[(i + 2) * 72 + jb];
            float2 u01 = rU[0], u23 = rU[1];
            float2 c01 = rC[0], c23 = rC[1];
            float2 d01 = rD[0], d23 = rD[1];
            float gx0 = ((u23.x - u01.x) + 2.0f * (c23.x - c01.x) + (d23.x - d01.x)) * 0.125f;
            float gy0 = ((d01.x - u01.x) + 2.0f * (d01.y - u01.y) + (d23.x - u23.x)) * 0.125f;
            float gx1 = ((u23.y - u01.y) + 2.0f * (c23.y - c01.y) + (d23.y - d01.y)) * 0.125f;
            float gy1 = ((d01.y - u01.y) + 2.0f * (d23.x - u23.x) + (d23.y - u23.y)) * 0.125f;
            mag_sector(gx0, gy0, m0, e0);
            mag_sector(gx1, gy1, m1, e1);
        }
        *(float2*)&s.bufA[i * 72 + jb] = make_float2(m0, m1);
        *(short2*)&s.sDel[i * 72 + jb] = make_short2(e0, e1);
    }
    __syncthreads();

    // ---- Stage 5: NMS mask (36 x 68). |delta| works: min(pos,neg) symmetric ----
    for (int i = ty; i < 36; i += 8) {
        bool yin = true;
        if (BORDER) yin = (unsigned)(y0 - 2 + i) < (unsigned)H;
#pragma unroll
        for (int jj = 0; jj < 3; ++jj) {
            int j = tx + jj * 32;
            if (jj < 2 || tx < 4) {
                float m = 0.0f;
                bool ok = true;
                if (BORDER) ok = yin && (unsigned)(x0 - 2 + j) < (unsigned)W;
                if (ok) {
                    int ci = (i + 1) * 72 + j + 1;
                    int d = s.sDel[ci];
                    float c = s.bufA[ci];
                    float p1 = s.bufA[ci + d];
                    float p2 = s.bufA[ci - d];
                    m = (c > p1 && c > p2) ? c : 0.0f;
                }
                s.bufB[i * 72 + j] = m;
            }
        }
    }
    __syncthreads();

    // ---- Stage 6: horizontal 5-max (36 x 64), float2 pairs ----
    for (int i = ty; i < 36; i += 8) {
        const float2* m2 = (const float2*)&s.bufB[i * 72];
        float2 a = m2[tx], b = m2[tx + 1], c = m2[tx + 2];
        float common = fmaxf(fmaxf(a.y, b.x), fmaxf(b.y, c.x));
        ((float2*)&s.bufC[i * 64])[tx] = make_float2(fmaxf(common, a.x), fmaxf(common, c.y));
    }
    __syncthreads();

    // ---- Stage 7: vertical 5-max, 4 contiguous rows/thread, float2 STG ----
    {
        const int r0o = ty * 4;
        float2 t[8];
#pragma unroll
        for (int r = 0; r < 8; ++r) t[r] = ((const float2*)&s.bufC[(r0o + r) * 64])[tx];
#pragma unroll
        for (int v = 0; v < 4; ++v) {
            float cx = fmaxf(fmaxf(t[v + 1].x, t[v + 2].x), fmaxf(t[v + 3].x, t[v + 4].x));
            float cy = fmaxf(fmaxf(t[v + 1].y, t[v + 2].y), fmaxf(t[v + 3].y, t[v + 4].y));
            float2 o = make_float2(fmaxf(cx, t[v].x), fmaxf(cy, t[v].y));
            *(float2*)&ob[(size_t)(y0 + r0o + v) * W + x0 + 2 * tx] = o;
        }
    }
}

__global__ __launch_bounds__(256) void canny_fused_kernel(
    const float* __restrict__ in, float* __restrict__ out) {
    __shared__ Smem s;
    const int bx = blockIdx.x, by = blockIdx.y;
    const int x0 = bx * 64, y0 = by * 32;
    const float* base = in + (size_t)blockIdx.z * 3 * PLANE;
    float* ob = out + (size_t)blockIdx.z * PLANE;
    const int tx = threadIdx.x & 31;
    const int ty = threadIdx.x >> 5;

    if (bx == 0 || bx == 7 || by == 0 || by == 15)
        canny_tile<true>(s, base, ob, x0, y0, tx, ty, threadIdx.x);
    else
        canny_tile<false>(s, base, ob, x0, y0, tx, ty, threadIdx.x);
}

extern "C" void kernel_launch(void* const* d_in, const int* in_sizes, int n_in,
                              void* d_out, int out_size) {
    const float* x = (const float*)d_in[0];
    float* out = (float*)d_out;
    dim3 grid(W / 64, H / 32, 32);
    canny_fused_kernel<<<grid, 256>>>(x, out);
}